// round 1
// baseline (speedup 1.0000x reference)
#include <cuda_runtime.h>
#include <cuda_bf16.h>
#include <cstdint>

// Instant-NGP hash grid encode.
// x: [B,3] in [-1,1] -> mapped to [0,1]; embeddings: [7131219, 2] fp32.
// out: [B, 32] fp32 (16 levels x 2 channels).

#define NPTS   524288
#define NLEV   16
#define HBASE  16
#define HMASK  0x7FFFFu          // 2^19 - 1 (hashed levels)
#define PRIME1 2654435761u
#define PRIME2 805459861u

// Cumulative level offsets (entries, not bytes).
__device__ __constant__ unsigned c_offs[NLEV] = {
    0u, 4913u, 40850u, 315475u,
    839763u, 1364051u, 1888339u, 2412627u,
    2936915u, 3461203u, 3985491u, 4509779u,
    5034067u, 5558355u, 6082643u, 6606931u
};

__global__ void __launch_bounds__(256, 4)
hash_encode_kernel(const float* __restrict__ in,
                   const float2* __restrict__ emb,
                   float* __restrict__ out)
{
    const int b = blockIdx.x * blockDim.x + threadIdx.x;
    if (b >= NPTS) return;

    // map [-1,1] -> [0,1], matching reference: (in + 1.0) / 2.0
    const float x = (in[3 * b + 0] + 1.0f) * 0.5f;
    const float y = (in[3 * b + 1] + 1.0f) * 0.5f;
    const float z = (in[3 * b + 2] + 1.0f) * 0.5f;

    float acc[2 * NLEV];

    #pragma unroll
    for (int l = 0; l < NLEV; ++l) {
        const int   res   = HBASE << l;
        const bool  dense = (l < 3);
        // dense table sizes: (res+1)^3
        const unsigned r1    = (unsigned)(res + 1);
        const unsigned hsize = dense ? (r1 * r1 * r1) : 524288u;

        const float fres = (float)res;
        const float px = x * fres, py = y * fres, pz = z * fres;
        const float gx = floorf(px), gy = floorf(py), gz = floorf(pz);
        const float tx = px - gx,   ty = py - gy,   tz = pz - gz;

        const unsigned ix = (unsigned)gx;
        const unsigned iy = (unsigned)gy;
        const unsigned iz = (unsigned)gz;

        const float wx[2] = {1.0f - tx, tx};
        const float wy[2] = {1.0f - ty, ty};
        const float wz[2] = {1.0f - tz, tz};

        const unsigned off = c_offs[l];
        float s0 = 0.0f, s1 = 0.0f;

        // corner order: bit0 = x, so (0,1),(2,3),(4,5),(6,7) are x-pairs.
        // Hashed levels: prime_x == 1 and hsize == 2^19, so when ix is even
        // the x-pair indices are idx and idx^1 -> same 32B sector (L1 absorbs
        // the second access; halves L2 sector traffic for those pairs).
        #pragma unroll
        for (int c = 0; c < 8; ++c) {
            const unsigned cx = (unsigned)(c & 1);
            const unsigned cy = (unsigned)((c >> 1) & 1);
            const unsigned cz = (unsigned)(c >> 2);
            const unsigned ux = ix + cx;
            const unsigned uy = iy + cy;
            const unsigned uz = iz + cz;

            unsigned idx;
            if (dense) {
                idx = (ux + uy * r1 + uz * r1 * r1) % hsize;
            } else {
                idx = (ux ^ (uy * PRIME1) ^ (uz * PRIME2)) & HMASK;
            }

            const float2 v = __ldg(&emb[off + idx]);
            const float  w = (wx[cx] * wy[cy]) * wz[cz];
            s0 += w * v.x;
            s1 += w * v.y;
        }
        acc[2 * l + 0] = s0;
        acc[2 * l + 1] = s1;
    }

    // Each thread owns exactly one 128B output line: 8 x STG.128.
    float4* o4 = reinterpret_cast<float4*>(out + (size_t)b * 32);
    #pragma unroll
    for (int i = 0; i < 8; ++i) {
        o4[i] = make_float4(acc[4 * i + 0], acc[4 * i + 1],
                            acc[4 * i + 2], acc[4 * i + 3]);
    }
}

extern "C" void kernel_launch(void* const* d_in, const int* in_sizes, int n_in,
                              void* d_out, int out_size)
{
    const float*  in  = (const float*)d_in[0];   // [B, 3]
    const float2* emb = (const float2*)d_in[1];  // [7131219, 2] read as float2
    float*        out = (float*)d_out;           // [B, 32]

    const int threads = 256;
    const int blocks  = (NPTS + threads - 1) / threads;  // 2048
    hash_encode_kernel<<<blocks, threads>>>(in, emb, out);
}